// round 4
// baseline (speedup 1.0000x reference)
#include <cuda_runtime.h>

// Problem constants
#define Bn 512
#define Dn 768
#define Ln 128
#define Rn 128
#define BD (Bn * Dn)        // floats per "l" slab
#define BD4 (BD / 4)
#define ROW4 (Dn / 4)       // 192
#define KC 32               // K chunk
#define TLD 132             // tile leading dim (padded)
#define NCHUNK (Dn / KC)    // 24
#define EPS 1e-4f

// Output offsets (floats), reference tuple order
#define LD_OFF 0ull
#define RD_OFF 50331648ull
#define LM_OFF 100663296ull
#define RM_OFF 100728832ull
#define LS_OFF 100794368ull
#define RS_OFF 100859904ull

// Scratch
__device__ float  g_invL[Ln * Dn];
__device__ float  g_invR[Rn * Dn];
__device__ double g_inv64L[Ln * Dn];
__device__ double g_inv64R[Rn * Dn];
__device__ int    g_lidx[Bn * Ln];
__device__ int    g_ridx[Bn * Rn];

// ---------------------------------------------------------------------------
// Kernel 1: inv_n[l,d] = 1/sqrt(sum_b x[l,b,d]^2), fp64 accumulation
// ---------------------------------------------------------------------------
__global__ __launch_bounds__(256) void norms_kernel(const float* __restrict__ left,
                                                    const float* __restrict__ right) {
    int gid = blockIdx.x * blockDim.x + threadIdx.x;
    const int LD = Ln * Dn;
    const float* src;
    float* dst32;
    double* dst64;
    int idx;
    if (gid < LD) { src = left;  dst32 = g_invL; dst64 = g_inv64L; idx = gid; }
    else          { src = right; dst32 = g_invR; dst64 = g_inv64R; idx = gid - LD; }
    int l = idx / Dn;
    int d = idx - l * Dn;
    const float* p = src + (size_t)l * BD + d;
    double acc = 0.0;
#pragma unroll 8
    for (int b = 0; b < Bn; b++) {
        double v = (double)p[(size_t)b * Dn];
        acc += v * v;
    }
    double inv = 1.0 / sqrt(acc);
    dst64[idx] = inv;
    dst32[idx] = (float)inv;
}

// ---------------------------------------------------------------------------
// Warp-collective fp64 normalized dot (all lanes return the total)
// ---------------------------------------------------------------------------
__device__ __forceinline__ double dot64(const float* __restrict__ left,
                                        const float* __restrict__ right,
                                        int l, int r, int b) {
    const int lane = threadIdx.x & 31;
    const float*  lp = left  + (size_t)l * BD + (size_t)b * Dn;
    const float*  rp = right + (size_t)r * BD + (size_t)b * Dn;
    const double* il = g_inv64L + l * Dn;
    const double* ir = g_inv64R + r * Dn;
    double acc = 0.0;
    for (int d = lane; d < Dn; d += 32)
        acc += (double)lp[d] * (double)rp[d] * il[d] * ir[d];
#pragma unroll
    for (int off = 16; off; off >>= 1)
        acc += __shfl_xor_sync(0xffffffffu, acc, off);
    return acc;
}

// ---------------------------------------------------------------------------
// Kernel 2: one CTA per batch b. Pipelined GEMM + masked max/argmax.
// ---------------------------------------------------------------------------
__global__ __launch_bounds__(256, 2) void main_kernel(const float* __restrict__ left,
                                                      const int*   __restrict__ llen,
                                                      const float* __restrict__ right,
                                                      const int*   __restrict__ rlen,
                                                      float*       __restrict__ out) {
    const int b   = blockIdx.x;
    const int tid = threadIdx.x;
    const int tx  = tid & 15;
    const int ty  = tid >> 4;

    __shared__ float lm[Ln];
    __shared__ float rm[Rn];

    extern __shared__ float smem[];
    // double-buffered tiles: [buf][As|Bs][KC][TLD]
    float* As[2] = { smem,               smem + 2 * KC * TLD };
    float* Bs[2] = { smem + KC * TLD,    smem + 3 * KC * TLD };
    float* att = smem;   // 128*129 floats, aliases tiles after GEMM

    // -------- Phase 1: masks --------
    {
        const int ll = llen[b];
        const int rl = rlen[b];
        if (tid < 128) {
            float lmv = (tid < ll) ? 1.0f : 0.0f;
            float rmv = (tid < rl) ? 1.0f : 0.0f;
            lm[tid] = lmv;
            rm[tid] = rmv;
            out[LM_OFF + (size_t)b * Ln + tid] = lmv;
            out[RM_OFF + (size_t)b * Rn + tid] = rmv;
        }
    }

    // -------- Phase 2: pipelined GEMM --------
    float acc[8][8];
#pragma unroll
    for (int i = 0; i < 8; i++)
#pragma unroll
        for (int j = 0; j < 8; j++) acc[i][j] = 0.f;

    const float* lbase = left  + (size_t)b * Dn;
    const float* rbase = right + (size_t)b * Dn;

    // per-thread load geometry (4 float4 per matrix per chunk)
    int rowv[4], dqv[4];
#pragma unroll
    for (int j = 0; j < 4; j++) {
        int i  = tid + 256 * j;
        rowv[j] = i >> 3;
        dqv[j]  = (i & 7) << 2;
    }

    float4 sva[4], svb[4];

    // stage chunk 0
#pragma unroll
    for (int j = 0; j < 4; j++) {
        sva[j] = *(const float4*)(lbase + (size_t)rowv[j] * BD + dqv[j]);
        svb[j] = *(const float4*)(rbase + (size_t)rowv[j] * BD + dqv[j]);
    }
    // normalize + store chunk 0
#pragma unroll
    for (int j = 0; j < 4; j++) {
        int dq = dqv[j], row = rowv[j];
        float4 na = *(const float4*)(g_invL + row * Dn + dq);
        As[0][(dq + 0) * TLD + row] = sva[j].x * na.x;
        As[0][(dq + 1) * TLD + row] = sva[j].y * na.y;
        As[0][(dq + 2) * TLD + row] = sva[j].z * na.z;
        As[0][(dq + 3) * TLD + row] = sva[j].w * na.w;
        float4 nb = *(const float4*)(g_invR + row * Dn + dq);
        Bs[0][(dq + 0) * TLD + row] = svb[j].x * nb.x;
        Bs[0][(dq + 1) * TLD + row] = svb[j].y * nb.y;
        Bs[0][(dq + 2) * TLD + row] = svb[j].z * nb.z;
        Bs[0][(dq + 3) * TLD + row] = svb[j].w * nb.w;
    }
    __syncthreads();

    for (int c = 0; c < NCHUNK; c++) {
        const int buf = c & 1;
        const int d1  = (c + 1) * KC;

        // issue next chunk's global loads (latency hidden behind compute)
        if (c + 1 < NCHUNK) {
#pragma unroll
            for (int j = 0; j < 4; j++) {
                sva[j] = *(const float4*)(lbase + (size_t)rowv[j] * BD + d1 + dqv[j]);
                svb[j] = *(const float4*)(rbase + (size_t)rowv[j] * BD + d1 + dqv[j]);
            }
        }

        // compute current chunk
        const float* ap = As[buf] + ty * 8;
        const float* bp = Bs[buf] + tx * 8;
#pragma unroll
        for (int kk = 0; kk < KC; kk++) {
            float4 a0 = *(const float4*)(ap + kk * TLD);
            float4 a1 = *(const float4*)(ap + kk * TLD + 4);
            float4 b0 = *(const float4*)(bp + kk * TLD);
            float4 b1 = *(const float4*)(bp + kk * TLD + 4);
            float a[8]  = {a0.x, a0.y, a0.z, a0.w, a1.x, a1.y, a1.z, a1.w};
            float bb[8] = {b0.x, b0.y, b0.z, b0.w, b1.x, b1.y, b1.z, b1.w};
#pragma unroll
            for (int i = 0; i < 8; i++)
#pragma unroll
                for (int j = 0; j < 8; j++)
                    acc[i][j] = fmaf(a[i], bb[j], acc[i][j]);
        }

        // normalize + store next chunk into the other buffer
        if (c + 1 < NCHUNK) {
            float* An = As[buf ^ 1];
            float* Bn_ = Bs[buf ^ 1];
#pragma unroll
            for (int j = 0; j < 4; j++) {
                int dq = dqv[j], row = rowv[j];
                float4 na = *(const float4*)(g_invL + row * Dn + d1 + dq);
                An[(dq + 0) * TLD + row] = sva[j].x * na.x;
                An[(dq + 1) * TLD + row] = sva[j].y * na.y;
                An[(dq + 2) * TLD + row] = sva[j].z * na.z;
                An[(dq + 3) * TLD + row] = sva[j].w * na.w;
                float4 nb = *(const float4*)(g_invR + row * Dn + d1 + dq);
                Bn_[(dq + 0) * TLD + row] = svb[j].x * nb.x;
                Bn_[(dq + 1) * TLD + row] = svb[j].y * nb.y;
                Bn_[(dq + 2) * TLD + row] = svb[j].z * nb.z;
                Bn_[(dq + 3) * TLD + row] = svb[j].w * nb.w;
            }
        }
        __syncthreads();
    }

    // -------- Phase 3: masked attention to smem --------
#pragma unroll
    for (int i = 0; i < 8; i++) {
        int row = ty * 8 + i;
        float lmv = lm[row];
#pragma unroll
        for (int j = 0; j < 8; j++) {
            int col = tx * 8 + j;
            att[row * 129 + col] = acc[i][j] * lmv * rm[col];
        }
    }
    __syncthreads();

    // -------- Phase 4: reductions with fp64 near-tie refinement --------
    const int warp = tid >> 5;
    const int lane = tid & 31;

    for (int r8 = 0; r8 < 16; r8++) {
        int row = warp * 16 + r8;
        float best = att[row * 129 + lane];
        int   bi   = lane;
#pragma unroll
        for (int m = 1; m < 4; m++) {
            float v = att[row * 129 + lane + 32 * m];
            if (v > best) { best = v; bi = lane + 32 * m; }
        }
#pragma unroll
        for (int off = 16; off; off >>= 1) {
            float ov = __shfl_xor_sync(0xffffffffu, best, off);
            int   oi = __shfl_xor_sync(0xffffffffu, bi,   off);
            if (ov > best || (ov == best && oi < bi)) { best = ov; bi = oi; }
        }
        float thr = best - EPS;
        int cnt = 0;
#pragma unroll
        for (int m = 0; m < 4; m++) {
            float v = att[row * 129 + m * 32 + lane];
            cnt += __popc(__ballot_sync(0xffffffffu, v >= thr));
        }
        int fi = bi;
        if (cnt >= 2) {
            bool zmode = (best == 0.0f);
            double bbest;
            int    bbi;
            if (zmode) { bbest = 0.0; bbi = bi; }
            else       { bbest = -1e300; bbi = -1; }
#pragma unroll
            for (int m = 0; m < 4; m++) {
                float v = att[row * 129 + m * 32 + lane];
                bool near = (v >= thr) && (!zmode || v != 0.0f);
                unsigned bal = __ballot_sync(0xffffffffu, near);
                while (bal) {
                    int ln = __ffs(bal) - 1;
                    bal &= bal - 1;
                    int cand = m * 32 + ln;
                    bool masked = (lm[row] == 0.0f) || (rm[cand] == 0.0f);
                    double val = masked ? 0.0 : dot64(left, right, row, cand, b);
                    if (val > bbest || (val == bbest && cand < bbi)) { bbest = val; bbi = cand; }
                }
            }
            fi = bbi;
        }
        if (lane == 0) {
            out[LS_OFF + (size_t)row * Bn + b] = att[row * 129 + fi];
            g_lidx[b * Ln + row] = fi;
        }
    }

    for (int c8 = 0; c8 < 16; c8++) {
        int col = warp * 16 + c8;
        float best = att[lane * 129 + col];
        int   bi   = lane;
#pragma unroll
        for (int m = 1; m < 4; m++) {
            float v = att[(lane + 32 * m) * 129 + col];
            if (v > best) { best = v; bi = lane + 32 * m; }
        }
#pragma unroll
        for (int off = 16; off; off >>= 1) {
            float ov = __shfl_xor_sync(0xffffffffu, best, off);
            int   oi = __shfl_xor_sync(0xffffffffu, bi,   off);
            if (ov > best || (ov == best && oi < bi)) { best = ov; bi = oi; }
        }
        float thr = best - EPS;
        int cnt = 0;
#pragma unroll
        for (int m = 0; m < 4; m++) {
            float v = att[(m * 32 + lane) * 129 + col];
            cnt += __popc(__ballot_sync(0xffffffffu, v >= thr));
        }
        int fi = bi;
        if (cnt >= 2) {
            bool zmode = (best == 0.0f);
            double bbest;
            int    bbi;
            if (zmode) { bbest = 0.0; bbi = bi; }
            else       { bbest = -1e300; bbi = -1; }
#pragma unroll
            for (int m = 0; m < 4; m++) {
                float v = att[(m * 32 + lane) * 129 + col];
                bool near = (v >= thr) && (!zmode || v != 0.0f);
                unsigned bal = __ballot_sync(0xffffffffu, near);
                while (bal) {
                    int ln = __ffs(bal) - 1;
                    bal &= bal - 1;
                    int cand = m * 32 + ln;
                    bool masked = (lm[cand] == 0.0f) || (rm[col] == 0.0f);
                    double val = masked ? 0.0 : dot64(left, right, cand, col, b);
                    if (val > bbest || (val == bbest && cand < bbi)) { bbest = val; bbi = cand; }
                }
            }
            fi = bbi;
        }
        if (lane == 0) {
            out[RS_OFF + (size_t)col * Bn + b] = att[fi * 129 + col];
            g_ridx[b * Rn + col] = fi;
        }
    }
}

// ---------------------------------------------------------------------------
// Kernel 3: difference gathers, pure streaming at full occupancy.
// One float4 per thread over both outputs.
// ---------------------------------------------------------------------------
__global__ __launch_bounds__(256) void diff_kernel(const float* __restrict__ left,
                                                   const int*   __restrict__ llen,
                                                   const float* __restrict__ right,
                                                   const int*   __restrict__ rlen,
                                                   float*       __restrict__ out) {
    const int PER_SIDE = Ln * Bn * ROW4;   // 12,582,912 float4
    int g = blockIdx.x * blockDim.x + threadIdx.x;
    bool isL = (g < PER_SIDE);
    int i4 = isL ? g : g - PER_SIDE;

    int l   = i4 / (Bn * ROW4);
    int rem = i4 - l * (Bn * ROW4);
    int b   = rem / ROW4;
    int dq  = rem - b * ROW4;

    const float4* l4 = (const float4*)left;
    const float4* r4 = (const float4*)right;

    float4 res = make_float4(0.f, 0.f, 0.f, 0.f);
    if (isL) {
        if (l < llen[b]) {
            int idx = g_lidx[b * Ln + l];
            float4 a = l4[i4];
            float4 c = r4[(size_t)idx * BD4 + (size_t)b * ROW4 + dq];
            res = make_float4(a.x - c.x, a.y - c.y, a.z - c.z, a.w - c.w);
        }
        ((float4*)(out + LD_OFF))[i4] = res;
    } else {
        if (l < rlen[b]) {
            int idx = g_ridx[b * Rn + l];
            float4 a = r4[i4];
            float4 c = l4[(size_t)idx * BD4 + (size_t)b * ROW4 + dq];
            res = make_float4(a.x - c.x, a.y - c.y, a.z - c.z, a.w - c.w);
        }
        ((float4*)(out + RD_OFF))[i4] = res;
    }
}

// ---------------------------------------------------------------------------
extern "C" void kernel_launch(void* const* d_in, const int* in_sizes, int n_in,
                              void* d_out, int out_size) {
    (void)in_sizes; (void)n_in; (void)out_size;
    const float* left  = (const float*)d_in[0];
    const int*   llen  = (const int*)d_in[1];
    const float* right = (const float*)d_in[2];
    const int*   rlen  = (const int*)d_in[3];
    float* out = (float*)d_out;

    const int SMEM = 4 * KC * TLD * sizeof(float);  // 67584 B (>= att 66048)
    cudaFuncSetAttribute(main_kernel, cudaFuncAttributeMaxDynamicSharedMemorySize, SMEM);

    norms_kernel<<<(2 * Ln * Dn) / 256, 256>>>(left, right);
    main_kernel<<<Bn, 256, SMEM>>>(left, llen, right, rlen, out);

    const int PER_SIDE = Ln * Bn * ROW4;
    diff_kernel<<<(2 * PER_SIDE) / 256, 256>>>(left, llen, right, rlen, out);
}

// round 5
// speedup vs baseline: 1.1764x; 1.1764x over previous
#include <cuda_runtime.h>

// Problem constants
#define Bn 512
#define Dn 768
#define Ln 128
#define Rn 128
#define BD (Bn * Dn)        // floats per "l" slab
#define BD4 (BD / 4)
#define ROW4 (Dn / 4)       // 192
#define KC 32               // K chunk
#define TLD 132             // tile leading dim (padded); 132*4B=528B, 16B-aligned rows
#define NCHUNK (Dn / KC)    // 24
#define EPS 1e-4f

// Output offsets (floats), reference tuple order
#define LD_OFF 0ull
#define RD_OFF 50331648ull
#define LM_OFF 100663296ull
#define RM_OFF 100728832ull
#define LS_OFF 100794368ull
#define RS_OFF 100859904ull

// Packed fp32x2 ops (Blackwell): FFMA2 reaches full fp32 rate (3-reg FFMA is half-rate)
#define PACK2(out, v)  asm("mov.b64 %0, {%1, %1};" : "=l"(out) : "f"(v))
#define FMA2(acc, a, b) asm("fma.rn.f32x2 %0, %1, %2, %0;" : "+l"(acc) : "l"(a), "l"(b))
#define UNPACK2(lo, hi, in) asm("mov.b64 {%0, %1}, %2;" : "=f"(lo), "=f"(hi) : "l"(in))

// Scratch
__device__ float  g_invL[Ln * Dn];
__device__ float  g_invR[Rn * Dn];
__device__ double g_inv64L[Ln * Dn];
__device__ double g_inv64R[Rn * Dn];
__device__ int    g_lidx[Bn * Ln];
__device__ int    g_ridx[Bn * Rn];

// ---------------------------------------------------------------------------
// Kernel 1: inv_n[l,d] = 1/sqrt(sum_b x[l,b,d]^2), fp64 accumulation
// ---------------------------------------------------------------------------
__global__ __launch_bounds__(256) void norms_kernel(const float* __restrict__ left,
                                                    const float* __restrict__ right) {
    int gid = blockIdx.x * blockDim.x + threadIdx.x;
    const int LD = Ln * Dn;
    const float* src;
    float* dst32;
    double* dst64;
    int idx;
    if (gid < LD) { src = left;  dst32 = g_invL; dst64 = g_inv64L; idx = gid; }
    else          { src = right; dst32 = g_invR; dst64 = g_inv64R; idx = gid - LD; }
    int l = idx / Dn;
    int d = idx - l * Dn;
    const float* p = src + (size_t)l * BD + d;
    double acc = 0.0;
#pragma unroll 8
    for (int b = 0; b < Bn; b++) {
        double v = (double)p[(size_t)b * Dn];
        acc += v * v;
    }
    double inv = 1.0 / sqrt(acc);
    dst64[idx] = inv;
    dst32[idx] = (float)inv;
}

// ---------------------------------------------------------------------------
// Warp-collective fp64 normalized dot (all lanes return the total)
// ---------------------------------------------------------------------------
__device__ __forceinline__ double dot64(const float* __restrict__ left,
                                        const float* __restrict__ right,
                                        int l, int r, int b) {
    const int lane = threadIdx.x & 31;
    const float*  lp = left  + (size_t)l * BD + (size_t)b * Dn;
    const float*  rp = right + (size_t)r * BD + (size_t)b * Dn;
    const double* il = g_inv64L + l * Dn;
    const double* ir = g_inv64R + r * Dn;
    double acc = 0.0;
    for (int d = lane; d < Dn; d += 32)
        acc += (double)lp[d] * (double)rp[d] * il[d] * ir[d];
#pragma unroll
    for (int off = 16; off; off >>= 1)
        acc += __shfl_xor_sync(0xffffffffu, acc, off);
    return acc;
}

// ---------------------------------------------------------------------------
// Kernel 2: one CTA per batch b. Pipelined FFMA2 GEMM + masked max/argmax.
// Length-aware: A rows >= ll and B rows >= rl are zero-filled (exact masked
// zeros), warps whose 16-row band is fully >= ll skip the FMA block entirely.
// ---------------------------------------------------------------------------
__global__ __launch_bounds__(256, 2) void main_kernel(const float* __restrict__ left,
                                                      const int*   __restrict__ llen,
                                                      const float* __restrict__ right,
                                                      const int*   __restrict__ rlen,
                                                      float*       __restrict__ out) {
    const int b   = blockIdx.x;
    const int tid = threadIdx.x;
    const int tx  = tid & 15;
    const int ty  = tid >> 4;

    __shared__ float lm[Ln];
    __shared__ float rm[Rn];

    extern __shared__ float smem[];
    // double-buffered tiles: [buf][As|Bs][KC][TLD]
    float* As[2] = { smem,               smem + 2 * KC * TLD };
    float* Bs[2] = { smem + KC * TLD,    smem + 3 * KC * TLD };
    float* att = smem;   // 128*129 floats, aliases tiles after GEMM

    const int ll = llen[b];
    const int rl = rlen[b];

    // -------- Phase 1: masks --------
    if (tid < 128) {
        float lmv = (tid < ll) ? 1.0f : 0.0f;
        float rmv = (tid < rl) ? 1.0f : 0.0f;
        lm[tid] = lmv;
        rm[tid] = rmv;
        out[LM_OFF + (size_t)b * Ln + tid] = lmv;
        out[RM_OFF + (size_t)b * Rn + tid] = rmv;
    }

    // -------- Phase 2: pipelined GEMM (FFMA2) --------
    // acc2[i][p]: pair of fp32 accumulators for cols tx*8 + 2p, 2p+1
    unsigned long long acc2[8][4];
#pragma unroll
    for (int i = 0; i < 8; i++)
#pragma unroll
        for (int p = 0; p < 4; p++) acc2[i][p] = 0ull;

    const float* lbase = left  + (size_t)b * Dn;
    const float* rbase = right + (size_t)b * Dn;

    // per-thread load geometry (4 float4 per matrix per chunk)
    int rowv[4], dqv[4];
#pragma unroll
    for (int j = 0; j < 4; j++) {
        int i  = tid + 256 * j;
        rowv[j] = i >> 3;
        dqv[j]  = (i & 7) << 2;
    }

    const float4 z4 = make_float4(0.f, 0.f, 0.f, 0.f);
    float4 sva[4], svb[4];

    // stage chunk 0 (zero-fill masked rows: exact masked zeros, less DRAM)
#pragma unroll
    for (int j = 0; j < 4; j++) {
        sva[j] = (rowv[j] < ll) ? *(const float4*)(lbase + (size_t)rowv[j] * BD + dqv[j]) : z4;
        svb[j] = (rowv[j] < rl) ? *(const float4*)(rbase + (size_t)rowv[j] * BD + dqv[j]) : z4;
    }
#pragma unroll
    for (int j = 0; j < 4; j++) {
        int dq = dqv[j], row = rowv[j];
        float4 na = *(const float4*)(g_invL + row * Dn + dq);
        As[0][(dq + 0) * TLD + row] = sva[j].x * na.x;
        As[0][(dq + 1) * TLD + row] = sva[j].y * na.y;
        As[0][(dq + 2) * TLD + row] = sva[j].z * na.z;
        As[0][(dq + 3) * TLD + row] = sva[j].w * na.w;
        float4 nb = *(const float4*)(g_invR + row * Dn + dq);
        Bs[0][(dq + 0) * TLD + row] = svb[j].x * nb.x;
        Bs[0][(dq + 1) * TLD + row] = svb[j].y * nb.y;
        Bs[0][(dq + 2) * TLD + row] = svb[j].z * nb.z;
        Bs[0][(dq + 3) * TLD + row] = svb[j].w * nb.w;
    }
    __syncthreads();

    // warp-uniform row-skip: warp covers rows [16w, 16w+16)
    const bool wact = (((tid >> 5) << 4) < ll);

    for (int c = 0; c < NCHUNK; c++) {
        const int buf = c & 1;
        const int d1  = (c + 1) * KC;

        // issue next chunk's global loads (latency hidden behind compute)
        if (c + 1 < NCHUNK) {
#pragma unroll
            for (int j = 0; j < 4; j++) {
                sva[j] = (rowv[j] < ll) ? *(const float4*)(lbase + (size_t)rowv[j] * BD + d1 + dqv[j]) : z4;
                svb[j] = (rowv[j] < rl) ? *(const float4*)(rbase + (size_t)rowv[j] * BD + d1 + dqv[j]) : z4;
            }
        }

        // compute current chunk (packed f32x2 FMA)
        if (wact) {
            const float* ap = As[buf] + ty * 8;
            const unsigned long long* bp64 =
                (const unsigned long long*)(Bs[buf] + tx * 8);   // 16B-aligned
#pragma unroll
            for (int kk = 0; kk < KC; kk++) {
                float4 a0 = *(const float4*)(ap + kk * TLD);
                float4 a1 = *(const float4*)(ap + kk * TLD + 4);
                ulonglong2 bA = *(const ulonglong2*)(bp64 + kk * 66);
                ulonglong2 bB = *(const ulonglong2*)(bp64 + kk * 66 + 2);
                unsigned long long bb0 = bA.x, bb1 = bA.y, bb2 = bB.x, bb3 = bB.y;
                float av[8] = {a0.x, a0.y, a0.z, a0.w, a1.x, a1.y, a1.z, a1.w};
#pragma unroll
                for (int i = 0; i < 8; i++) {
                    unsigned long long aa;
                    PACK2(aa, av[i]);
                    FMA2(acc2[i][0], aa, bb0);
                    FMA2(acc2[i][1], aa, bb1);
                    FMA2(acc2[i][2], aa, bb2);
                    FMA2(acc2[i][3], aa, bb3);
                }
            }
        }

        // normalize + store next chunk into the other buffer
        if (c + 1 < NCHUNK) {
            float* An = As[buf ^ 1];
            float* Bn_ = Bs[buf ^ 1];
#pragma unroll
            for (int j = 0; j < 4; j++) {
                int dq = dqv[j], row = rowv[j];
                float4 na = *(const float4*)(g_invL + row * Dn + d1 + dq);
                An[(dq + 0) * TLD + row] = sva[j].x * na.x;
                An[(dq + 1) * TLD + row] = sva[j].y * na.y;
                An[(dq + 2) * TLD + row] = sva[j].z * na.z;
                An[(dq + 3) * TLD + row] = sva[j].w * na.w;
                float4 nb = *(const float4*)(g_invR + row * Dn + d1 + dq);
                Bn_[(dq + 0) * TLD + row] = svb[j].x * nb.x;
                Bn_[(dq + 1) * TLD + row] = svb[j].y * nb.y;
                Bn_[(dq + 2) * TLD + row] = svb[j].z * nb.z;
                Bn_[(dq + 3) * TLD + row] = svb[j].w * nb.w;
            }
        }
        __syncthreads();
    }

    // -------- Phase 3: masked attention to smem --------
#pragma unroll
    for (int i = 0; i < 8; i++) {
        int row = ty * 8 + i;
        float lmv = lm[row];
#pragma unroll
        for (int p = 0; p < 4; p++) {
            float lo, hi;
            UNPACK2(lo, hi, acc2[i][p]);
            int col = tx * 8 + 2 * p;
            att[row * 129 + col]     = lo * lmv * rm[col];
            att[row * 129 + col + 1] = hi * lmv * rm[col + 1];
        }
    }
    __syncthreads();

    // -------- Phase 4: reductions with fp64 near-tie refinement --------
    const int warp = tid >> 5;
    const int lane = tid & 31;

    for (int r8 = 0; r8 < 16; r8++) {
        int row = warp * 16 + r8;
        float best = att[row * 129 + lane];
        int   bi   = lane;
#pragma unroll
        for (int m = 1; m < 4; m++) {
            float v = att[row * 129 + lane + 32 * m];
            if (v > best) { best = v; bi = lane + 32 * m; }
        }
#pragma unroll
        for (int off = 16; off; off >>= 1) {
            float ov = __shfl_xor_sync(0xffffffffu, best, off);
            int   oi = __shfl_xor_sync(0xffffffffu, bi,   off);
            if (ov > best || (ov == best && oi < bi)) { best = ov; bi = oi; }
        }
        float thr = best - EPS;
        int cnt = 0;
#pragma unroll
        for (int m = 0; m < 4; m++) {
            float v = att[row * 129 + m * 32 + lane];
            cnt += __popc(__ballot_sync(0xffffffffu, v >= thr));
        }
        int fi = bi;
        if (cnt >= 2) {
            bool zmode = (best == 0.0f);
            double bbest;
            int    bbi;
            if (zmode) { bbest = 0.0; bbi = bi; }
            else       { bbest = -1e300; bbi = -1; }
#pragma unroll
            for (int m = 0; m < 4; m++) {
                float v = att[row * 129 + m * 32 + lane];
                bool near = (v >= thr) && (!zmode || v != 0.0f);
                unsigned bal = __ballot_sync(0xffffffffu, near);
                while (bal) {
                    int ln = __ffs(bal) - 1;
                    bal &= bal - 1;
                    int cand = m * 32 + ln;
                    bool masked = (lm[row] == 0.0f) || (rm[cand] == 0.0f);
                    double val = masked ? 0.0 : dot64(left, right, row, cand, b);
                    if (val > bbest || (val == bbest && cand < bbi)) { bbest = val; bbi = cand; }
                }
            }
            fi = bbi;
        }
        if (lane == 0) {
            out[LS_OFF + (size_t)row * Bn + b] = att[row * 129 + fi];
            g_lidx[b * Ln + row] = fi;
        }
    }

    for (int c8 = 0; c8 < 16; c8++) {
        int col = warp * 16 + c8;
        float best = att[lane * 129 + col];
        int   bi   = lane;
#pragma unroll
        for (int m = 1; m < 4; m++) {
            float v = att[(lane + 32 * m) * 129 + col];
            if (v > best) { best = v; bi = lane + 32 * m; }
        }
#pragma unroll
        for (int off = 16; off; off >>= 1) {
            float ov = __shfl_xor_sync(0xffffffffu, best, off);
            int   oi = __shfl_xor_sync(0xffffffffu, bi,   off);
            if (ov > best || (ov == best && oi < bi)) { best = ov; bi = oi; }
        }
        float thr = best - EPS;
        int cnt = 0;
#pragma unroll
        for (int m = 0; m < 4; m++) {
            float v = att[(m * 32 + lane) * 129 + col];
            cnt += __popc(__ballot_sync(0xffffffffu, v >= thr));
        }
        int fi = bi;
        if (cnt >= 2) {
            bool zmode = (best == 0.0f);
            double bbest;
            int    bbi;
            if (zmode) { bbest = 0.0; bbi = bi; }
            else       { bbest = -1e300; bbi = -1; }
#pragma unroll
            for (int m = 0; m < 4; m++) {
                float v = att[(m * 32 + lane) * 129 + col];
                bool near = (v >= thr) && (!zmode || v != 0.0f);
                unsigned bal = __ballot_sync(0xffffffffu, near);
                while (bal) {
                    int ln = __ffs(bal) - 1;
                    bal &= bal - 1;
                    int cand = m * 32 + ln;
                    bool masked = (lm[cand] == 0.0f) || (rm[col] == 0.0f);
                    double val = masked ? 0.0 : dot64(left, right, cand, col, b);
                    if (val > bbest || (val == bbest && cand < bbi)) { bbest = val; bbi = cand; }
                }
            }
            fi = bbi;
        }
        if (lane == 0) {
            out[RS_OFF + (size_t)col * Bn + b] = att[fi * 129 + col];
            g_ridx[b * Rn + col] = fi;
        }
    }
}

// ---------------------------------------------------------------------------
// Kernel 3: difference gathers, pure streaming at full occupancy.
// ---------------------------------------------------------------------------
__global__ __launch_bounds__(256) void diff_kernel(const float* __restrict__ left,
                                                   const int*   __restrict__ llen,
                                                   const float* __restrict__ right,
                                                   const int*   __restrict__ rlen,
                                                   float*       __restrict__ out) {
    const int PER_SIDE = Ln * Bn * ROW4;   // 12,582,912 float4
    int g = blockIdx.x * blockDim.x + threadIdx.x;
    bool isL = (g < PER_SIDE);
    int i4 = isL ? g : g - PER_SIDE;

    int l   = i4 / (Bn * ROW4);
    int rem = i4 - l * (Bn * ROW4);
    int b   = rem / ROW4;
    int dq  = rem - b * ROW4;

    const float4* l4 = (const float4*)left;
    const float4* r4 = (const float4*)right;

    float4 res = make_float4(0.f, 0.f, 0.f, 0.f);
    if (isL) {
        if (l < llen[b]) {
            int idx = g_lidx[b * Ln + l];
            float4 a = l4[i4];
            float4 c = r4[(size_t)idx * BD4 + (size_t)b * ROW4 + dq];
            res = make_float4(a.x - c.x, a.y - c.y, a.z - c.z, a.w - c.w);
        }
        ((float4*)(out + LD_OFF))[i4] = res;
    } else {
        if (l < rlen[b]) {
            int idx = g_ridx[b * Rn + l];
            float4 a = r4[i4];
            float4 c = l4[(size_t)idx * BD4 + (size_t)b * ROW4 + dq];
            res = make_float4(a.x - c.x, a.y - c.y, a.z - c.z, a.w - c.w);
        }
        ((float4*)(out + RD_OFF))[i4] = res;
    }
}

// ---------------------------------------------------------------------------
extern "C" void kernel_launch(void* const* d_in, const int* in_sizes, int n_in,
                              void* d_out, int out_size) {
    (void)in_sizes; (void)n_in; (void)out_size;
    const float* left  = (const float*)d_in[0];
    const int*   llen  = (const int*)d_in[1];
    const float* right = (const float*)d_in[2];
    const int*   rlen  = (const int*)d_in[3];
    float* out = (float*)d_out;

    const int SMEM = 4 * KC * TLD * sizeof(float);  // 67584 B (>= att 66048)
    cudaFuncSetAttribute(main_kernel, cudaFuncAttributeMaxDynamicSharedMemorySize, SMEM);

    norms_kernel<<<(2 * Ln * Dn) / 256, 256>>>(left, right);
    main_kernel<<<Bn, 256, SMEM>>>(left, llen, right, rlen, out);

    const int PER_SIDE = Ln * Bn * ROW4;
    diff_kernel<<<(2 * PER_SIDE) / 256, 256>>>(left, llen, right, rlen, out);
}